// round 6
// baseline (speedup 1.0000x reference)
#include <cuda_runtime.h>
#include <cstdint>

// ---------------------------------------------------------------------------
// MaskAttention: B=2, S=3144, C=256, H=8, HD=32, QN=8, image 56x56, lepe 5x5 dw
// R6: R5 with the fragment-buffer sizing bug fixed (1024 float2 entries per
//     tile, 4 entries per thread). LDS.64 conflict-free MMA operands,
//     cp.async mask double-buffer, shuffle P-transform.
// softmax(qk + log(m+eps)) == (m+eps)*exp(qk) / sum_k (m+eps)*exp(qk)
// ---------------------------------------------------------------------------

#define B_   2
#define S_   3144
#define C_   256
#define H_   8
#define HD_  32
#define QN_  8
#define IMH_ 56
#define IMW_ 56
#define SCALE_ 0.17677669529663687f   // 32^-0.5

__device__ __align__(16) float g_q[B_*S_*C_];
__device__ __align__(16) float g_k[B_*S_*C_];
__device__ __align__(16) float g_v[B_*S_*C_];
__device__ __align__(16) float g_att[B_*S_*C_];

// ----------------------------- helpers -------------------------------------
__device__ __forceinline__ uint32_t tf32r(float x) {
    uint32_t r;
    asm("cvt.rna.tf32.f32 %0, %1;" : "=r"(r) : "f"(x));
    return r;
}
__device__ __forceinline__ void mma_tf32(float* d, const uint32_t* a,
                                         uint32_t b0, uint32_t b1) {
    asm volatile(
        "mma.sync.aligned.m16n8k8.row.col.f32.tf32.tf32.f32 "
        "{%0,%1,%2,%3}, {%4,%5,%6,%7}, {%8,%9}, {%0,%1,%2,%3};"
        : "+f"(d[0]), "+f"(d[1]), "+f"(d[2]), "+f"(d[3])
        : "r"(a[0]), "r"(a[1]), "r"(a[2]), "r"(a[3]), "r"(b0), "r"(b1));
}
__device__ __forceinline__ float pexp(float s) {
    float p = fmaf(s, 1.f/24.f, 1.f/6.f);
    p = fmaf(p, s, 0.5f);
    p = fmaf(p, s, 1.f);
    return fmaf(p, s, 1.f);
}
__device__ __forceinline__ uint32_t smem_u32(const void* p) {
    uint32_t a;
    asm("{ .reg .u64 t; cvta.to.shared.u64 t, %1; cvt.u32.u64 %0, t; }"
        : "=r"(a) : "l"(p));
    return a;
}
#define CP_ASYNC16(dst, src, sz) \
    asm volatile("cp.async.ca.shared.global [%0], [%1], 16, %2;" \
                 :: "r"(dst), "l"(src), "r"(sz) : "memory")
#define CP_COMMIT() asm volatile("cp.async.commit_group;" ::: "memory")
#define CP_WAIT0()  asm volatile("cp.async.wait_group 0;" ::: "memory")

// ---------------------------------------------------------------------------
// Projection GEMM (tf32 mma): C[M,256] = (A[M,256] @ W[256,256]^T + bias)*scale
// (unchanged from R4)
// ---------------------------------------------------------------------------
__global__ __launch_bounds__(256, 2) void gemm_mma_kernel(
    const float* __restrict__ Aext, const float* __restrict__ W,
    const float* __restrict__ bias, float* __restrict__ Cext,
    int src_att, int dst_sel, int M, float scale)
{
    __shared__ float As[128][36];
    __shared__ float Ws[64][36];
    const float* A = src_att ? g_att : Aext;
    float* Cm = (dst_sel == 0) ? g_q : (dst_sel == 1) ? g_k
              : (dst_sel == 2) ? g_v : Cext;

    const int m0 = blockIdx.x * 128, n0 = blockIdx.y * 64;
    const int t = threadIdx.x, w = t >> 5, lane = t & 31;
    const int g = lane >> 2, c = lane & 3;
    const int row0 = m0 + w * 16 + g, row1 = row0 + 8;

    float acc[8][4] = {};

    for (int k0 = 0; k0 < 256; k0 += 32) {
        __syncthreads();
        #pragma unroll
        for (int i = t; i < 1024; i += 256) {
            int r = i >> 3, sg = i & 7;
            int gm = m0 + r;
            float4 vv = make_float4(0.f, 0.f, 0.f, 0.f);
            if (gm < M) vv = *(const float4*)(A + (size_t)gm * 256 + k0 + sg * 4);
            uint4 u;
            u.x = tf32r(vv.x); u.y = tf32r(vv.y); u.z = tf32r(vv.z); u.w = tf32r(vv.w);
            *(uint4*)&As[r][sg * 4] = u;
        }
        #pragma unroll
        for (int i = t; i < 512; i += 256) {
            int r = i >> 3, sg = i & 7;
            float4 vv = *(const float4*)(W + (size_t)(n0 + r) * 256 + k0 + sg * 4);
            uint4 u;
            u.x = tf32r(vv.x); u.y = tf32r(vv.y); u.z = tf32r(vv.z); u.w = tf32r(vv.w);
            *(uint4*)&Ws[r][sg * 4] = u;
        }
        __syncthreads();

        #pragma unroll
        for (int ks = 0; ks < 4; ks++) {
            uint32_t a[4];
            a[0] = __float_as_uint(As[w*16 + g    ][ks*8 + c    ]);
            a[1] = __float_as_uint(As[w*16 + g + 8][ks*8 + c    ]);
            a[2] = __float_as_uint(As[w*16 + g    ][ks*8 + c + 4]);
            a[3] = __float_as_uint(As[w*16 + g + 8][ks*8 + c + 4]);
            #pragma unroll
            for (int nt = 0; nt < 8; nt++) {
                uint32_t b0 = __float_as_uint(Ws[nt*8 + g][ks*8 + c    ]);
                uint32_t b1 = __float_as_uint(Ws[nt*8 + g][ks*8 + c + 4]);
                mma_tf32(acc[nt], a, b0, b1);
            }
        }
    }

    #pragma unroll
    for (int nt = 0; nt < 8; nt++) {
        int n = n0 + nt * 8 + 2 * c;
        float2 bb = *(const float2*)(bias + n);
        if (row0 < M) {
            float2 r;
            r.x = (acc[nt][0] + bb.x) * scale;
            r.y = (acc[nt][1] + bb.y) * scale;
            *(float2*)(Cm + (size_t)row0 * 256 + n) = r;
        }
        if (row1 < M) {
            float2 r;
            r.x = (acc[nt][2] + bb.x) * scale;
            r.y = (acc[nt][3] + bb.y) * scale;
            *(float2*)(Cm + (size_t)row1 * 256 + n) = r;
        }
    }
}

// ---------------------------------------------------------------------------
// Attention. CTA = 128 queries x 1 head, 8 warps x 16 rows, 50 key tiles of 64.
// Dynamic smem:
//   kb1[2][1024] float2  (MMA1 B-frags, entry e = nt*128+ks*32+lane:
//                         {K[nt8+(lane>>2)][ks8+(lane&3)], same row dim+4})
//   kb2[2][1024] float2  (MMA2 B-frags, entry e = nt*128+nt2*32+lane:
//                         {K[nt8+(lane&3)][nt2_8+(lane>>2)], row+4 same dim})
//   Ms [2][8][16][68]    (mask tiles, cp.async)
// total = 16384 + 16384 + 69632 = 102400 bytes
// ---------------------------------------------------------------------------
#define MSK_F   8192     // float index base of mask region
#define MSK_BUF 8704     // floats per mask buffer
#define SMEM_ATTN 102400
#define NT_TILES 50

__global__ __launch_bounds__(256, 2) void attn_mma_kernel(const float* __restrict__ maskp)
{
    extern __shared__ __align__(16) float ds[];
    float2* const kb1 = (float2*)ds;            // [2][1024]
    float2* const kb2 = (float2*)ds + 2048;     // [2][1024]

    const int q0 = blockIdx.x * 128;
    const int h  = blockIdx.y;
    const int b  = blockIdx.z;
    const int t = threadIdx.x, w = t >> 5, lane = t & 31;
    const int g = lane >> 2, c = lane & 3;
    const int row0 = q0 + w * 16 + g, row1 = row0 + 8;
    const bool v0 = row0 < S_, v1 = row1 < S_;

    const float* qb = g_q + (size_t)b * S_ * C_ + h * HD_;
    const float* kb = g_k + (size_t)b * S_ * C_ + h * HD_;
    const float* mb = maskp + (size_t)b * S_ * S_;

    // Q fragments (persist)
    uint32_t qa[4][4];
    #pragma unroll
    for (int ks = 0; ks < 4; ks++) {
        int d0 = ks * 8 + c;
        qa[ks][0] = v0 ? tf32r(qb[(size_t)row0 * C_ + d0    ]) : 0u;
        qa[ks][1] = v1 ? tf32r(qb[(size_t)row1 * C_ + d0    ]) : 0u;
        qa[ks][2] = v0 ? tf32r(qb[(size_t)row0 * C_ + d0 + 4]) : 0u;
        qa[ks][3] = v1 ? tf32r(qb[(size_t)row1 * C_ + d0 + 4]) : 0u;
    }

    // ---- K fragment entries owned by this thread: e_i = t + 256*i, i=0..3.
    // lane and (t>>5)&3 are invariant across i; nt_i = (t>>7) + 2*i.
    const int ksq = (t >> 5) & 3;          // kb1: ks slot; kb2: nt2 slot
    const int ntb = (t >> 7);              // 0 or 1
    const int d1  = ksq * 8 + c;           // kb1 column (dim)
    const int d2  = ksq * 8 + g;           // kb2 column (dim)
    // kb1 row_i  = (ntb + 2i)*8 + g  (within tile)
    // kb2 row_i  = (ntb + 2i)*8 + c

    // ---- mask cp.async destinations ----
    uint32_t msmem[8];
    {
        uint32_t base = smem_u32(ds + MSK_F);
        #pragma unroll
        for (int jj = 0; jj < 8; jj++) {
            int j = jj * 32 + lane;
            int row = j >> 4, col4 = j & 15;
            msmem[jj] = base + (uint32_t)(((w * 16 + row) * 68 + col4 * 4) * 4);
        }
    }
    const uint32_t msbuf_bytes = MSK_BUF * 4u;

    // issue mask(0) prefetch
    #pragma unroll
    for (int jj = 0; jj < 8; jj++) {
        int j = jj * 32 + lane;
        int row = j >> 4, col4 = j & 15;
        int grow = q0 + w * 16 + row;
        uint32_t sz = (grow < S_) ? 16u : 0u;
        const float* src = mb + (size_t)(sz ? grow : 0) * S_ + col4 * 4;
        CP_ASYNC16(msmem[jj], src, sz);
    }
    CP_COMMIT();

    // ---- load K tile 0 into fragment buffers (all rows < S_) ----
    #pragma unroll
    for (int i = 0; i < 4; i++) {
        int r1 = (ntb + 2 * i) * 8 + g;
        int r2 = (ntb + 2 * i) * 8 + c;
        float a0 = kb[(size_t)r1 * C_ + d1];
        float a1 = kb[(size_t)r1 * C_ + d1 + 4];
        float b0 = kb[(size_t)r2 * C_ + d2];
        float b1 = kb[(size_t)(r2 + 4) * C_ + d2];
        kb1[t + 256 * i] = make_float2(__uint_as_float(tf32r(a0)), __uint_as_float(tf32r(a1)));
        kb2[t + 256 * i] = make_float2(__uint_as_float(tf32r(b0)), __uint_as_float(tf32r(b1)));
    }

    float o[4][4] = {};
    float den0 = 0.f, den1 = 0.f;

    for (int kt = 0; kt < NT_TILES; kt++) {
        const int k0 = kt * 64;
        const int cur = kt & 1;
        CP_WAIT0();
        __syncthreads();   // current K frag buffers + mask buffer ready

        // ---- prefetch next tile (mask via cp.async, K into regs) ----
        float p1x[4], p1y[4], p2x[4], p2y[4];
        if (kt < NT_TILES - 1) {
            const int nk0 = k0 + 64;
            uint32_t boff = (uint32_t)(cur ^ 1) * msbuf_bytes;
            #pragma unroll
            for (int jj = 0; jj < 8; jj++) {
                int j = jj * 32 + lane;
                int row = j >> 4, col4 = j & 15;
                int grow = q0 + w * 16 + row;
                int gcol = nk0 + col4 * 4;
                uint32_t sz = (grow < S_ && gcol < S_) ? 16u : 0u;
                const float* src = mb + (size_t)(sz ? grow : 0) * S_ + (sz ? gcol : 0);
                CP_ASYNC16(msmem[jj] + boff, src, sz);
            }
            CP_COMMIT();
            #pragma unroll
            for (int i = 0; i < 4; i++) {
                int r1 = nk0 + (ntb + 2 * i) * 8 + g;
                int r2 = nk0 + (ntb + 2 * i) * 8 + c;
                p1x[i] = (r1 < S_) ? kb[(size_t)r1 * C_ + d1    ] : 0.f;
                p1y[i] = (r1 < S_) ? kb[(size_t)r1 * C_ + d1 + 4] : 0.f;
                p2x[i] = (r2     < S_) ? kb[(size_t)r2 * C_ + d2]       : 0.f;
                p2y[i] = (r2 + 4 < S_) ? kb[(size_t)(r2 + 4) * C_ + d2] : 0.f;
            }
        }

        const float2* kb1c = kb1 + cur * 1024;
        const float2* kb2c = kb2 + cur * 1024;
        const float*  Msc  = ds + MSK_F + (size_t)cur * MSK_BUF + (size_t)w * 16 * 68;

        #pragma unroll
        for (int nt = 0; nt < 8; nt++) {
            // MMA1: s = Q * Ktile^T for this 8-key group (LDS.64 operands)
            float s[4] = {0.f, 0.f, 0.f, 0.f};
            #pragma unroll
            for (int ks = 0; ks < 4; ks++) {
                float2 bb = kb1c[(nt * 4 + ks) * 32 + lane];
                mma_tf32(s, qa[ks], __float_as_uint(bb.x), __float_as_uint(bb.y));
            }
            // softmax weights (S_ % 8 == 0 -> group all-valid or all-OOB)
            const bool kv = (k0 + nt * 8) < S_;
            float w0 = 0.f, w1 = 0.f, w2 = 0.f, w3 = 0.f;
            if (kv) {
                if (v0) {
                    float2 mm = *(const float2*)&Msc[g * 68 + nt*8 + 2*c];
                    w0 = (mm.x + 1e-6f) * pexp(s[0]);
                    w1 = (mm.y + 1e-6f) * pexp(s[1]);
                }
                if (v1) {
                    float2 mm = *(const float2*)&Msc[(g + 8) * 68 + nt*8 + 2*c];
                    w2 = (mm.x + 1e-6f) * pexp(s[2]);
                    w3 = (mm.y + 1e-6f) * pexp(s[3]);
                }
            }
            den0 += w0 + w1;
            den1 += w2 + w3;

            // P C-frag -> MMA2 A-frag via intra-quad shuffles
            uint32_t t0 = tf32r(w0), t1 = tf32r(w1), t2 = tf32r(w2), t3 = tf32r(w3);
            int slo = (lane & ~3) | (c >> 1);
            int shi = slo + 2;
            uint32_t a[4], e0, e1;
            e0 = __shfl_sync(0xffffffffu, t0, slo);
            e1 = __shfl_sync(0xffffffffu, t1, slo);
            a[0] = (c & 1) ? e1 : e0;
            e0 = __shfl_sync(0xffffffffu, t2, slo);
            e1 = __shfl_sync(0xffffffffu, t3, slo);
            a[1] = (c & 1) ? e1 : e0;
            e0 = __shfl_sync(0xffffffffu, t0, shi);
            e1 = __shfl_sync(0xffffffffu, t1, shi);
            a[2] = (c & 1) ? e1 : e0;
            e0 = __shfl_sync(0xffffffffu, t2, shi);
            e1 = __shfl_sync(0xffffffffu, t3, shi);
            a[3] = (c & 1) ? e1 : e0;

            // MMA2: O += P(group nt) * Ktile rows nt*8..+7 (LDS.64 operands)
            #pragma unroll
            for (int nt2 = 0; nt2 < 4; nt2++) {
                float2 bb = kb2c[(nt * 4 + nt2) * 32 + lane];
                mma_tf32(o[nt2], a, __float_as_uint(bb.x), __float_as_uint(bb.y));
            }
        }

        // ---- store prefetched K(kt+1) fragments to the other buffer ----
        if (kt < NT_TILES - 1) {
            float2* kb1n = kb1 + (cur ^ 1) * 1024;
            float2* kb2n = kb2 + (cur ^ 1) * 1024;
            #pragma unroll
            for (int i = 0; i < 4; i++) {
                kb1n[t + 256 * i] = make_float2(__uint_as_float(tf32r(p1x[i])),
                                                __uint_as_float(tf32r(p1y[i])));
                kb2n[t + 256 * i] = make_float2(__uint_as_float(tf32r(p2x[i])),
                                                __uint_as_float(tf32r(p2y[i])));
            }
        }
    }

    // denominator: reduce across the 4 lanes of each row-group
    den0 += __shfl_xor_sync(0xffffffffu, den0, 1);
    den0 += __shfl_xor_sync(0xffffffffu, den0, 2);
    den1 += __shfl_xor_sync(0xffffffffu, den1, 1);
    den1 += __shfl_xor_sync(0xffffffffu, den1, 2);
    const float inv0 = v0 ? 1.f / den0 : 0.f;
    const float inv1 = v1 ? 1.f / den1 : 0.f;

    float* ob0 = g_att + ((size_t)b * S_ + row0) * C_ + h * HD_;
    float* ob1 = g_att + ((size_t)b * S_ + row1) * C_ + h * HD_;
    #pragma unroll
    for (int nt2 = 0; nt2 < 4; nt2++) {
        if (v0) {
            float2 r;
            r.x = o[nt2][0] * inv0;
            r.y = o[nt2][1] * inv0;
            *(float2*)(ob0 + nt2 * 8 + 2 * c) = r;
        }
        if (v1) {
            float2 r;
            r.x = o[nt2][2] * inv1;
            r.y = o[nt2][3] * inv1;
            *(float2*)(ob1 + nt2 * 8 + 2 * c) = r;
        }
    }
}

// ---------------------------------------------------------------------------
// LEPE: depthwise 5x5 conv on v[:, QN:, :], pad 2, added into g_att[:, QN:, :]
// ---------------------------------------------------------------------------
__global__ __launch_bounds__(256) void lepe_kernel(
    const float* __restrict__ lw, const float* __restrict__ lb)
{
    int p = blockIdx.x;
    int b = blockIdx.y;
    int c = threadIdx.x;
    int i = p / IMW_, j = p % IMW_;

    float acc = lb[c];
    #pragma unroll
    for (int u = 0; u < 5; u++) {
        int ii = i + u - 2;
        if (ii < 0 || ii >= IMH_) continue;
        #pragma unroll
        for (int v = 0; v < 5; v++) {
            int jj = j + v - 2;
            if (jj < 0 || jj >= IMW_) continue;
            int src = QN_ + ii * IMW_ + jj;
            acc += g_v[((size_t)b * S_ + src) * C_ + c] * lw[(u * 5 + v) * C_ + c];
        }
    }
    g_att[((size_t)b * S_ + QN_ + p) * C_ + c] += acc;
}

// ---------------------------------------------------------------------------
extern "C" void kernel_launch(void* const* d_in, const int* in_sizes, int n_in,
                              void* d_out, int out_size)
{
    const float* x    = (const float*)d_in[0];
    const float* mask = (const float*)d_in[1];
    const float* wq   = (const float*)d_in[2];
    const float* bq   = (const float*)d_in[3];
    const float* wk   = (const float*)d_in[4];
    const float* bk   = (const float*)d_in[5];
    const float* wv   = (const float*)d_in[6];
    const float* bv   = (const float*)d_in[7];
    const float* lw   = (const float*)d_in[8];
    const float* lb   = (const float*)d_in[9];
    const float* wo   = (const float*)d_in[10];
    const float* bo   = (const float*)d_in[11];
    float* out = (float*)d_out;

    const int M = B_ * S_;                       // 6288
    dim3 gg((M + 127) / 128, C_ / 64);           // 50 x 4

    static int smem_set = 0;
    if (!smem_set) {
        cudaFuncSetAttribute(attn_mma_kernel,
                             cudaFuncAttributeMaxDynamicSharedMemorySize, SMEM_ATTN);
        smem_set = 1;
    }

    gemm_mma_kernel<<<gg, 256>>>(x, wq, bq, nullptr, 0, 0, M, 1.f);
    gemm_mma_kernel<<<gg, 256>>>(x, wk, bk, nullptr, 0, 1, M, SCALE_);
    gemm_mma_kernel<<<gg, 256>>>(x, wv, bv, nullptr, 0, 2, M, 1.f);

    attn_mma_kernel<<<dim3((S_ + 127) / 128, H_, B_), 256, SMEM_ATTN>>>(mask);

    lepe_kernel<<<dim3(IMH_ * IMW_, B_), 256>>>(lw, lb);

    gemm_mma_kernel<<<gg, 256>>>(nullptr, wo, bo, out, 1, 3, M, 1.f);
}

// round 7
// speedup vs baseline: 1.3377x; 1.3377x over previous
#include <cuda_runtime.h>
#include <cstdint>

// ---------------------------------------------------------------------------
// MaskAttention: B=2, S=3144, C=256, H=8, HD=32, QN=8, image 56x56, lepe 5x5 dw
// R7: R4 base + (a) 4 warps x 32 q-rows (two m16 groups per warp, B-frag loads
//     shared by 2 MMAs), (b) transposed K copy for conflict-free MMA2 operands.
// softmax(qk + log(m+eps)) == (m+eps)*exp(qk) / sum_k (m+eps)*exp(qk)
// ---------------------------------------------------------------------------

#define B_   2
#define S_   3144
#define C_   256
#define H_   8
#define HD_  32
#define QN_  8
#define IMH_ 56
#define IMW_ 56
#define SCALE_ 0.17677669529663687f   // 32^-0.5

__device__ __align__(16) float g_q[B_*S_*C_];
__device__ __align__(16) float g_k[B_*S_*C_];
__device__ __align__(16) float g_v[B_*S_*C_];
__device__ __align__(16) float g_att[B_*S_*C_];

// ----------------------------- helpers -------------------------------------
__device__ __forceinline__ uint32_t tf32r(float x) {
    uint32_t r;
    asm("cvt.rna.tf32.f32 %0, %1;" : "=r"(r) : "f"(x));
    return r;
}
__device__ __forceinline__ void mma_tf32(float* d, const uint32_t* a,
                                         uint32_t b0, uint32_t b1) {
    asm volatile(
        "mma.sync.aligned.m16n8k8.row.col.f32.tf32.tf32.f32 "
        "{%0,%1,%2,%3}, {%4,%5,%6,%7}, {%8,%9}, {%0,%1,%2,%3};"
        : "+f"(d[0]), "+f"(d[1]), "+f"(d[2]), "+f"(d[3])
        : "r"(a[0]), "r"(a[1]), "r"(a[2]), "r"(a[3]), "r"(b0), "r"(b1));
}
__device__ __forceinline__ float pexp(float s) {
    float p = fmaf(s, 1.f/24.f, 1.f/6.f);
    p = fmaf(p, s, 0.5f);
    p = fmaf(p, s, 1.f);
    return fmaf(p, s, 1.f);
}
__device__ __forceinline__ uint32_t smem_u32(const void* p) {
    uint32_t a;
    asm("{ .reg .u64 t; cvta.to.shared.u64 t, %1; cvt.u32.u64 %0, t; }"
        : "=r"(a) : "l"(p));
    return a;
}
#define CP_ASYNC16(dst, src, sz) \
    asm volatile("cp.async.ca.shared.global [%0], [%1], 16, %2;" \
                 :: "r"(dst), "l"(src), "r"(sz) : "memory")
#define CP_COMMIT() asm volatile("cp.async.commit_group;" ::: "memory")
#define CP_WAIT0()  asm volatile("cp.async.wait_group 0;" ::: "memory")

// ---------------------------------------------------------------------------
// Projection GEMM (tf32 mma): C[M,256] = (A[M,256] @ W[256,256]^T + bias)*scale
// (unchanged from R4)
// ---------------------------------------------------------------------------
__global__ __launch_bounds__(256, 2) void gemm_mma_kernel(
    const float* __restrict__ Aext, const float* __restrict__ W,
    const float* __restrict__ bias, float* __restrict__ Cext,
    int src_att, int dst_sel, int M, float scale)
{
    __shared__ float As[128][36];
    __shared__ float Ws[64][36];
    const float* A = src_att ? g_att : Aext;
    float* Cm = (dst_sel == 0) ? g_q : (dst_sel == 1) ? g_k
              : (dst_sel == 2) ? g_v : Cext;

    const int m0 = blockIdx.x * 128, n0 = blockIdx.y * 64;
    const int t = threadIdx.x, w = t >> 5, lane = t & 31;
    const int g = lane >> 2, c = lane & 3;
    const int row0 = m0 + w * 16 + g, row1 = row0 + 8;

    float acc[8][4] = {};

    for (int k0 = 0; k0 < 256; k0 += 32) {
        __syncthreads();
        #pragma unroll
        for (int i = t; i < 1024; i += 256) {
            int r = i >> 3, sg = i & 7;
            int gm = m0 + r;
            float4 vv = make_float4(0.f, 0.f, 0.f, 0.f);
            if (gm < M) vv = *(const float4*)(A + (size_t)gm * 256 + k0 + sg * 4);
            uint4 u;
            u.x = tf32r(vv.x); u.y = tf32r(vv.y); u.z = tf32r(vv.z); u.w = tf32r(vv.w);
            *(uint4*)&As[r][sg * 4] = u;
        }
        #pragma unroll
        for (int i = t; i < 512; i += 256) {
            int r = i >> 3, sg = i & 7;
            float4 vv = *(const float4*)(W + (size_t)(n0 + r) * 256 + k0 + sg * 4);
            uint4 u;
            u.x = tf32r(vv.x); u.y = tf32r(vv.y); u.z = tf32r(vv.z); u.w = tf32r(vv.w);
            *(uint4*)&Ws[r][sg * 4] = u;
        }
        __syncthreads();

        #pragma unroll
        for (int ks = 0; ks < 4; ks++) {
            uint32_t a[4];
            a[0] = __float_as_uint(As[w*16 + g    ][ks*8 + c    ]);
            a[1] = __float_as_uint(As[w*16 + g + 8][ks*8 + c    ]);
            a[2] = __float_as_uint(As[w*16 + g    ][ks*8 + c + 4]);
            a[3] = __float_as_uint(As[w*16 + g + 8][ks*8 + c + 4]);
            #pragma unroll
            for (int nt = 0; nt < 8; nt++) {
                uint32_t b0 = __float_as_uint(Ws[nt*8 + g][ks*8 + c    ]);
                uint32_t b1 = __float_as_uint(Ws[nt*8 + g][ks*8 + c + 4]);
                mma_tf32(acc[nt], a, b0, b1);
            }
        }
    }

    #pragma unroll
    for (int nt = 0; nt < 8; nt++) {
        int n = n0 + nt * 8 + 2 * c;
        float2 bb = *(const float2*)(bias + n);
        if (row0 < M) {
            float2 r;
            r.x = (acc[nt][0] + bb.x) * scale;
            r.y = (acc[nt][1] + bb.y) * scale;
            *(float2*)(Cm + (size_t)row0 * 256 + n) = r;
        }
        if (row1 < M) {
            float2 r;
            r.x = (acc[nt][2] + bb.x) * scale;
            r.y = (acc[nt][3] + bb.y) * scale;
            *(float2*)(Cm + (size_t)row1 * 256 + n) = r;
        }
    }
}

// ---------------------------------------------------------------------------
// Attention. CTA = 128 queries x 1 head. 4 warps x 32 q rows. 50 key tiles.
// Dynamic smem (float indices):
//   Ks [2][64][36]  @ 0      (K tile, [key][dim], MMA1 B operands)
//   KsT[2][32][68]  @ 4608   (K tile transposed [dim][key], MMA2 B operands)
//   Ms [2][128][68] @ 8960   (mask tiles, cp.async)
// total = (4608 + 4352 + 17408) * 4 = 105472 bytes  -> 2 CTAs/SM
// ---------------------------------------------------------------------------
#define KST_F   4608
#define MSK_F   8960
#define MSK_BUF 8704
#define SMEM_ATTN 105472
#define NT_TILES 50

__global__ __launch_bounds__(128, 2) void attn_mma_kernel(const float* __restrict__ maskp)
{
    extern __shared__ __align__(16) float ds[];

    const int q0 = blockIdx.x * 128;
    const int h  = blockIdx.y;
    const int b  = blockIdx.z;
    const int t = threadIdx.x, w = t >> 5, lane = t & 31;
    const int g = lane >> 2, c = lane & 3;

    // two q row-groups per warp
    const int r00 = q0 + w * 32 + g,      r01 = r00 + 8;    // group 0
    const int r10 = q0 + w * 32 + 16 + g, r11 = r10 + 8;    // group 1
    const bool v00 = r00 < S_, v01 = r01 < S_;
    const bool v10 = r10 < S_, v11 = r11 < S_;

    const float* qb = g_q + (size_t)b * S_ * C_ + h * HD_;
    const float* kb = g_k + (size_t)b * S_ * C_ + h * HD_;
    const float* mb = maskp + (size_t)b * S_ * S_;

    // Q fragments for both groups (persist)
    uint32_t qa0[4][4], qa1[4][4];
    #pragma unroll
    for (int ks = 0; ks < 4; ks++) {
        int d0 = ks * 8 + c;
        qa0[ks][0] = v00 ? tf32r(qb[(size_t)r00 * C_ + d0    ]) : 0u;
        qa0[ks][1] = v01 ? tf32r(qb[(size_t)r01 * C_ + d0    ]) : 0u;
        qa0[ks][2] = v00 ? tf32r(qb[(size_t)r00 * C_ + d0 + 4]) : 0u;
        qa0[ks][3] = v01 ? tf32r(qb[(size_t)r01 * C_ + d0 + 4]) : 0u;
        qa1[ks][0] = v10 ? tf32r(qb[(size_t)r10 * C_ + d0    ]) : 0u;
        qa1[ks][1] = v11 ? tf32r(qb[(size_t)r11 * C_ + d0    ]) : 0u;
        qa1[ks][2] = v10 ? tf32r(qb[(size_t)r10 * C_ + d0 + 4]) : 0u;
        qa1[ks][3] = v11 ? tf32r(qb[(size_t)r11 * C_ + d0 + 4]) : 0u;
    }

    const uint32_t mskbase = smem_u32(ds + MSK_F);
    const uint32_t msbuf_bytes = MSK_BUF * 4u;

    // ---- issue mask(0) prefetch: 2048 16B-chunks over 128 threads ----
    #pragma unroll
    for (int jj = 0; jj < 16; jj++) {
        int j = jj * 128 + t;
        int row = j >> 4, col4 = j & 15;
        int grow = q0 + row;
        uint32_t dst = mskbase + (uint32_t)((row * 68 + col4 * 4) * 4);
        uint32_t sz = (grow < S_) ? 16u : 0u;
        const float* src = mb + (size_t)(sz ? grow : 0) * S_ + col4 * 4;
        CP_ASYNC16(dst, src, sz);
    }
    CP_COMMIT();

    // ---- load K tile 0 into Ks + KsT (keys 0..63 all valid) ----
    #pragma unroll
    for (int i = 0; i < 4; i++) {
        int idx = t + 128 * i;
        int row = idx >> 3, sg = idx & 7;
        float4 vv = *(const float4*)(kb + (size_t)row * C_ + sg * 4);
        uint4 u;
        u.x = tf32r(vv.x); u.y = tf32r(vv.y); u.z = tf32r(vv.z); u.w = tf32r(vv.w);
        *(uint4*)&ds[row * 36 + sg * 4] = u;
        ds[KST_F + (sg*4 + 0) * 68 + row] = __uint_as_float(u.x);
        ds[KST_F + (sg*4 + 1) * 68 + row] = __uint_as_float(u.y);
        ds[KST_F + (sg*4 + 2) * 68 + row] = __uint_as_float(u.z);
        ds[KST_F + (sg*4 + 3) * 68 + row] = __uint_as_float(u.w);
    }

    float o0[4][4] = {}, o1[4][4] = {};
    float den00 = 0.f, den01 = 0.f, den10 = 0.f, den11 = 0.f;

    for (int kt = 0; kt < NT_TILES; kt++) {
        const int k0 = kt * 64;
        const int cur = kt & 1;
        CP_WAIT0();
        __syncthreads();   // Ks/KsT[cur] + mask[cur] ready

        // ---- prefetch next tile ----
        float4 pk[4];
        if (kt < NT_TILES - 1) {
            const int nk0 = k0 + 64;
            uint32_t boff = (uint32_t)(cur ^ 1) * msbuf_bytes;
            #pragma unroll
            for (int jj = 0; jj < 16; jj++) {
                int j = jj * 128 + t;
                int row = j >> 4, col4 = j & 15;
                int grow = q0 + row;
                int gcol = nk0 + col4 * 4;
                uint32_t dst = mskbase + boff + (uint32_t)((row * 68 + col4 * 4) * 4);
                uint32_t sz = (grow < S_ && gcol < S_) ? 16u : 0u;
                const float* src = mb + (size_t)(sz ? grow : 0) * S_ + (sz ? gcol : 0);
                CP_ASYNC16(dst, src, sz);
            }
            CP_COMMIT();
            #pragma unroll
            for (int i = 0; i < 4; i++) {
                int idx = t + 128 * i;
                int row = nk0 + (idx >> 3), sg = idx & 7;
                pk[i] = make_float4(0.f, 0.f, 0.f, 0.f);
                if (row < S_) pk[i] = *(const float4*)(kb + (size_t)row * C_ + sg * 4);
            }
        }

        const float* Ksc  = ds + cur * 2304;
        const float* KsTc = ds + KST_F + cur * 2176;
        const float* Msk  = ds + MSK_F + (size_t)cur * MSK_BUF;
        const int qr0 = w * 32 + g;        // smem mask row for group0/r0

        #pragma unroll
        for (int nt = 0; nt < 8; nt++) {
            // ---- MMA1 for both q groups, shared B fragments ----
            float s0[4] = {0.f, 0.f, 0.f, 0.f};
            float s1[4] = {0.f, 0.f, 0.f, 0.f};
            #pragma unroll
            for (int ks = 0; ks < 4; ks++) {
                uint32_t b0 = __float_as_uint(Ksc[(nt*8 + g) * 36 + ks*8 + c    ]);
                uint32_t b1 = __float_as_uint(Ksc[(nt*8 + g) * 36 + ks*8 + c + 4]);
                mma_tf32(s0, qa0[ks], b0, b1);
                mma_tf32(s1, qa1[ks], b0, b1);
            }
            // ---- softmax weights (8-key group all-valid or all-OOB) ----
            const bool kv = (k0 + nt * 8) < S_;
            float w00 = 0.f, w01 = 0.f, w02 = 0.f, w03 = 0.f;
            float w10 = 0.f, w11 = 0.f, w12 = 0.f, w13 = 0.f;
            if (kv) {
                const int mc = nt * 8 + 2 * c;
                if (v00) {
                    float2 mm = *(const float2*)&Msk[(qr0     ) * 68 + mc];
                    w00 = (mm.x + 1e-6f) * pexp(s0[0]);
                    w01 = (mm.y + 1e-6f) * pexp(s0[1]);
                }
                if (v01) {
                    float2 mm = *(const float2*)&Msk[(qr0 +  8) * 68 + mc];
                    w02 = (mm.x + 1e-6f) * pexp(s0[2]);
                    w03 = (mm.y + 1e-6f) * pexp(s0[3]);
                }
                if (v10) {
                    float2 mm = *(const float2*)&Msk[(qr0 + 16) * 68 + mc];
                    w10 = (mm.x + 1e-6f) * pexp(s1[0]);
                    w11 = (mm.y + 1e-6f) * pexp(s1[1]);
                }
                if (v11) {
                    float2 mm = *(const float2*)&Msk[(qr0 + 24) * 68 + mc];
                    w12 = (mm.x + 1e-6f) * pexp(s1[2]);
                    w13 = (mm.y + 1e-6f) * pexp(s1[3]);
                }
            }
            den00 += w00 + w01;  den01 += w02 + w03;
            den10 += w10 + w11;  den11 += w12 + w13;

            // ---- P C-frag -> MMA2 A-frag via intra-quad shuffles (x2 groups) --
            const int slo = (lane & ~3) | (c >> 1);
            const int shi = slo + 2;
            uint32_t a0[4], a1[4], e0, e1;
            {
                uint32_t t0 = tf32r(w00), t1 = tf32r(w01), t2 = tf32r(w02), t3 = tf32r(w03);
                e0 = __shfl_sync(0xffffffffu, t0, slo);
                e1 = __shfl_sync(0xffffffffu, t1, slo);
                a0[0] = (c & 1) ? e1 : e0;
                e0 = __shfl_sync(0xffffffffu, t2, slo);
                e1 = __shfl_sync(0xffffffffu, t3, slo);
                a0[1] = (c & 1) ? e1 : e0;
                e0 = __shfl_sync(0xffffffffu, t0, shi);
                e1 = __shfl_sync(0xffffffffu, t1, shi);
                a0[2] = (c & 1) ? e1 : e0;
                e0 = __shfl_sync(0xffffffffu, t2, shi);
                e1 = __shfl_sync(0xffffffffu, t3, shi);
                a0[3] = (c & 1) ? e1 : e0;
            }
            {
                uint32_t t0 = tf32r(w10), t1 = tf32r(w11), t2 = tf32r(w12), t3 = tf32r(w13);
                e0 = __shfl_sync(0xffffffffu, t0, slo);
                e1 = __shfl_sync(0xffffffffu, t1, slo);
                a1[0] = (c & 1) ? e1 : e0;
                e0 = __shfl_sync(0xffffffffu, t2, slo);
                e1 = __shfl_sync(0xffffffffu, t3, slo);
                a1[1] = (c & 1) ? e1 : e0;
                e0 = __shfl_sync(0xffffffffu, t0, shi);
                e1 = __shfl_sync(0xffffffffu, t1, shi);
                a1[2] = (c & 1) ? e1 : e0;
                e0 = __shfl_sync(0xffffffffu, t2, shi);
                e1 = __shfl_sync(0xffffffffu, t3, shi);
                a1[3] = (c & 1) ? e1 : e0;
            }

            // ---- MMA2 for both groups, shared B fragments (KsT, conflict-free)
            #pragma unroll
            for (int nt2 = 0; nt2 < 4; nt2++) {
                uint32_t b0 = __float_as_uint(KsTc[(nt2*8 + g) * 68 + nt*8 + c    ]);
                uint32_t b1 = __float_as_uint(KsTc[(nt2*8 + g) * 68 + nt*8 + c + 4]);
                mma_tf32(o0[nt2], a0, b0, b1);
                mma_tf32(o1[nt2], a1, b0, b1);
            }
        }

        // ---- store prefetched K(kt+1) into the other buffers ----
        if (kt < NT_TILES - 1) {
            float* Ksn  = ds + (cur ^ 1) * 2304;
            float* KsTn = ds + KST_F + (cur ^ 1) * 2176;
            #pragma unroll
            for (int i = 0; i < 4; i++) {
                int idx = t + 128 * i;
                int row = idx >> 3, sg = idx & 7;
                uint4 u;
                u.x = tf32r(pk[i].x); u.y = tf32r(pk[i].y);
                u.z = tf32r(pk[i].z); u.w = tf32r(pk[i].w);
                *(uint4*)&Ksn[row * 36 + sg * 4] = u;
                KsTn[(sg*4 + 0) * 68 + row] = __uint_as_float(u.x);
                KsTn[(sg*4 + 1) * 68 + row] = __uint_as_float(u.y);
                KsTn[(sg*4 + 2) * 68 + row] = __uint_as_float(u.z);
                KsTn[(sg*4 + 3) * 68 + row] = __uint_as_float(u.w);
            }
        }
    }

    // ---- denominators: reduce across the 4 lanes of each row-group ----
    den00 += __shfl_xor_sync(0xffffffffu, den00, 1);
    den00 += __shfl_xor_sync(0xffffffffu, den00, 2);
    den01 += __shfl_xor_sync(0xffffffffu, den01, 1);
    den01 += __shfl_xor_sync(0xffffffffu, den01, 2);
    den10 += __shfl_xor_sync(0xffffffffu, den10, 1);
    den10 += __shfl_xor_sync(0xffffffffu, den10, 2);
    den11 += __shfl_xor_sync(0xffffffffu, den11, 1);
    den11 += __shfl_xor_sync(0xffffffffu, den11, 2);
    const float i00 = v00 ? 1.f / den00 : 0.f;
    const float i01 = v01 ? 1.f / den01 : 0.f;
    const float i10 = v10 ? 1.f / den10 : 0.f;
    const float i11 = v11 ? 1.f / den11 : 0.f;

    float* base = g_att + (size_t)b * S_ * C_ + h * HD_;
    #pragma unroll
    for (int nt2 = 0; nt2 < 4; nt2++) {
        int nn = nt2 * 8 + 2 * c;
        if (v00) {
            float2 r; r.x = o0[nt2][0] * i00; r.y = o0[nt2][1] * i00;
            *(float2*)(base + (size_t)r00 * C_ + nn) = r;
        }
        if (v01) {
            float2 r; r.x = o0[nt2][2] * i01; r.y = o0[nt2][3] * i01;
            *(float2*)(base + (size_t)r01 * C_ + nn) = r;
        }
        if (v10) {
            float2 r; r.x = o1[nt2][0] * i10; r.y = o1[nt2][1] * i10;
            *(float2*)(base + (size_t)r10 * C_ + nn) = r;
        }
        if (v11) {
            float2 r; r.x = o1[nt2][2] * i11; r.y = o1[nt2][3] * i11;
            *(float2*)(base + (size_t)r11 * C_ + nn) = r;
        }
    }
}

// ---------------------------------------------------------------------------
// LEPE: depthwise 5x5 conv on v[:, QN:, :], pad 2, added into g_att[:, QN:, :]
// ---------------------------------------------------------------------------
__global__ __launch_bounds__(256) void lepe_kernel(
    const float* __restrict__ lw, const float* __restrict__ lb)
{
    int p = blockIdx.x;
    int b = blockIdx.y;
    int c = threadIdx.x;
    int i = p / IMW_, j = p % IMW_;

    float acc = lb[c];
    #pragma unroll
    for (int u = 0; u < 5; u++) {
        int ii = i + u - 2;
        if (ii < 0 || ii >= IMH_) continue;
        #pragma unroll
        for (int v = 0; v < 5; v++) {
            int jj = j + v - 2;
            if (jj < 0 || jj >= IMW_) continue;
            int src = QN_ + ii * IMW_ + jj;
            acc += g_v[((size_t)b * S_ + src) * C_ + c] * lw[(u * 5 + v) * C_ + c];
        }
    }
    g_att[((size_t)b * S_ + QN_ + p) * C_ + c] += acc;
}

// ---------------------------------------------------------------------------
extern "C" void kernel_launch(void* const* d_in, const int* in_sizes, int n_in,
                              void* d_out, int out_size)
{
    const float* x    = (const float*)d_in[0];
    const float* mask = (const float*)d_in[1];
    const float* wq   = (const float*)d_in[2];
    const float* bq   = (const float*)d_in[3];
    const float* wk   = (const float*)d_in[4];
    const float* bk   = (const float*)d_in[5];
    const float* wv   = (const float*)d_in[6];
    const float* bv   = (const float*)d_in[7];
    const float* lw   = (const float*)d_in[8];
    const float* lb   = (const float*)d_in[9];
    const float* wo   = (const float*)d_in[10];
    const float* bo   = (const float*)d_in[11];
    float* out = (float*)d_out;

    const int M = B_ * S_;                       // 6288
    dim3 gg((M + 127) / 128, C_ / 64);           // 50 x 4

    static int smem_set = 0;
    if (!smem_set) {
        cudaFuncSetAttribute(attn_mma_kernel,
                             cudaFuncAttributeMaxDynamicSharedMemorySize, SMEM_ATTN);
        smem_set = 1;
    }

    gemm_mma_kernel<<<gg, 256>>>(x, wq, bq, nullptr, 0, 0, M, 1.f);
    gemm_mma_kernel<<<gg, 256>>>(x, wk, bk, nullptr, 0, 1, M, SCALE_);
    gemm_mma_kernel<<<gg, 256>>>(x, wv, bv, nullptr, 0, 2, M, 1.f);

    attn_mma_kernel<<<dim3((S_ + 127) / 128, H_, B_), 128, SMEM_ATTN>>>(mask);

    lepe_kernel<<<dim3(IMH_ * IMW_, B_), 256>>>(lw, lb);

    gemm_mma_kernel<<<gg, 256>>>(nullptr, wo, bo, out, 1, 3, M, 1.f);
}

// round 8
// speedup vs baseline: 1.8436x; 1.3782x over previous
#include <cuda_runtime.h>
#include <cstdint>

// ---------------------------------------------------------------------------
// MaskAttention: B=2, S=3144, C=256, H=8, HD=32, QN=8, image 56x56, lepe 5x5 dw
// R8: R4 base (8 warps x 16 q-rows, cp.async mask double-buffer, reg-buffered
//     K) + key-permutation inside 8-key groups so MMA1's C-fragment IS MMA2's
//     A-fragment (all shuffles eliminated) + transposed KsT for conflict-free
//     MMA2 B operands.
// softmax(qk + log(m+eps)) == (m+eps)*exp(qk) / sum_k (m+eps)*exp(qk)
// ---------------------------------------------------------------------------

#define B_   2
#define S_   3144
#define C_   256
#define H_   8
#define HD_  32
#define QN_  8
#define IMH_ 56
#define IMW_ 56
#define SCALE_ 0.17677669529663687f   // 32^-0.5

__device__ __align__(16) float g_q[B_*S_*C_];
__device__ __align__(16) float g_k[B_*S_*C_];
__device__ __align__(16) float g_v[B_*S_*C_];
__device__ __align__(16) float g_att[B_*S_*C_];

// ----------------------------- helpers -------------------------------------
__device__ __forceinline__ uint32_t tf32r(float x) {
    uint32_t r;
    asm("cvt.rna.tf32.f32 %0, %1;" : "=r"(r) : "f"(x));
    return r;
}
__device__ __forceinline__ void mma_tf32(float* d, const uint32_t* a,
                                         uint32_t b0, uint32_t b1) {
    asm volatile(
        "mma.sync.aligned.m16n8k8.row.col.f32.tf32.tf32.f32 "
        "{%0,%1,%2,%3}, {%4,%5,%6,%7}, {%8,%9}, {%0,%1,%2,%3};"
        : "+f"(d[0]), "+f"(d[1]), "+f"(d[2]), "+f"(d[3])
        : "r"(a[0]), "r"(a[1]), "r"(a[2]), "r"(a[3]), "r"(b0), "r"(b1));
}
__device__ __forceinline__ float pexp(float s) {
    float p = fmaf(s, 1.f/24.f, 1.f/6.f);
    p = fmaf(p, s, 0.5f);
    p = fmaf(p, s, 1.f);
    return fmaf(p, s, 1.f);
}
__device__ __forceinline__ uint32_t smem_u32(const void* p) {
    uint32_t a;
    asm("{ .reg .u64 t; cvta.to.shared.u64 t, %1; cvt.u32.u64 %0, t; }"
        : "=r"(a) : "l"(p));
    return a;
}
#define CP_ASYNC16(dst, src, sz) \
    asm volatile("cp.async.ca.shared.global [%0], [%1], 16, %2;" \
                 :: "r"(dst), "l"(src), "r"(sz) : "memory")
#define CP_COMMIT() asm volatile("cp.async.commit_group;" ::: "memory")
#define CP_WAIT0()  asm volatile("cp.async.wait_group 0;" ::: "memory")

// ---------------------------------------------------------------------------
// Projection GEMM (tf32 mma): C[M,256] = (A[M,256] @ W[256,256]^T + bias)*scale
// ---------------------------------------------------------------------------
__global__ __launch_bounds__(256, 2) void gemm_mma_kernel(
    const float* __restrict__ Aext, const float* __restrict__ W,
    const float* __restrict__ bias, float* __restrict__ Cext,
    int src_att, int dst_sel, int M, float scale)
{
    __shared__ float As[128][36];
    __shared__ float Ws[64][36];
    const float* A = src_att ? g_att : Aext;
    float* Cm = (dst_sel == 0) ? g_q : (dst_sel == 1) ? g_k
              : (dst_sel == 2) ? g_v : Cext;

    const int m0 = blockIdx.x * 128, n0 = blockIdx.y * 64;
    const int t = threadIdx.x, w = t >> 5, lane = t & 31;
    const int g = lane >> 2, c = lane & 3;
    const int row0 = m0 + w * 16 + g, row1 = row0 + 8;

    float acc[8][4] = {};

    for (int k0 = 0; k0 < 256; k0 += 32) {
        __syncthreads();
        #pragma unroll
        for (int i = t; i < 1024; i += 256) {
            int r = i >> 3, sg = i & 7;
            int gm = m0 + r;
            float4 vv = make_float4(0.f, 0.f, 0.f, 0.f);
            if (gm < M) vv = *(const float4*)(A + (size_t)gm * 256 + k0 + sg * 4);
            uint4 u;
            u.x = tf32r(vv.x); u.y = tf32r(vv.y); u.z = tf32r(vv.z); u.w = tf32r(vv.w);
            *(uint4*)&As[r][sg * 4] = u;
        }
        #pragma unroll
        for (int i = t; i < 512; i += 256) {
            int r = i >> 3, sg = i & 7;
            float4 vv = *(const float4*)(W + (size_t)(n0 + r) * 256 + k0 + sg * 4);
            uint4 u;
            u.x = tf32r(vv.x); u.y = tf32r(vv.y); u.z = tf32r(vv.z); u.w = tf32r(vv.w);
            *(uint4*)&Ws[r][sg * 4] = u;
        }
        __syncthreads();

        #pragma unroll
        for (int ks = 0; ks < 4; ks++) {
            uint32_t a[4];
            a[0] = __float_as_uint(As[w*16 + g    ][ks*8 + c    ]);
            a[1] = __float_as_uint(As[w*16 + g + 8][ks*8 + c    ]);
            a[2] = __float_as_uint(As[w*16 + g    ][ks*8 + c + 4]);
            a[3] = __float_as_uint(As[w*16 + g + 8][ks*8 + c + 4]);
            #pragma unroll
            for (int nt = 0; nt < 8; nt++) {
                uint32_t b0 = __float_as_uint(Ws[nt*8 + g][ks*8 + c    ]);
                uint32_t b1 = __float_as_uint(Ws[nt*8 + g][ks*8 + c + 4]);
                mma_tf32(acc[nt], a, b0, b1);
            }
        }
    }

    #pragma unroll
    for (int nt = 0; nt < 8; nt++) {
        int n = n0 + nt * 8 + 2 * c;
        float2 bb = *(const float2*)(bias + n);
        if (row0 < M) {
            float2 r;
            r.x = (acc[nt][0] + bb.x) * scale;
            r.y = (acc[nt][1] + bb.y) * scale;
            *(float2*)(Cm + (size_t)row0 * 256 + n) = r;
        }
        if (row1 < M) {
            float2 r;
            r.x = (acc[nt][2] + bb.x) * scale;
            r.y = (acc[nt][3] + bb.y) * scale;
            *(float2*)(Cm + (size_t)row1 * 256 + n) = r;
        }
    }
}

// ---------------------------------------------------------------------------
// Attention. CTA = 128 queries x 1 head, 8 warps x 16 rows, 50 key tiles of 64.
// Dynamic smem (float indices):
//   Ks [2][64][36]  @ 0      (K tile [key][dim], MMA1 B operands)
//   KsT[2][32][68]  @ 4608   (K tile [dim][key], MMA2 B operands, conflict-free)
//   Ms [2][8][16][68] @ 8960 (mask tiles, cp.async, per-warp 16-row blocks)
// total = (8960 + 17408) * 4 = 105472 bytes -> 2 CTAs/SM (211KB of 228KB)
// Key-group permutation p = {0,4,1,5,2,6,3,7}: MMA1 B row = nt*8 + p(g), so
// S column j holds key p(j); then C-frag slots map to A-frag slots directly.
// ---------------------------------------------------------------------------
#define KST_F   4608
#define MSK_F   8960
#define MSK_BUF 8704
#define SMEM_ATTN 105472
#define NT_TILES 50

__global__ __launch_bounds__(256, 2) void attn_mma_kernel(const float* __restrict__ maskp)
{
    extern __shared__ __align__(16) float ds[];

    const int q0 = blockIdx.x * 128;
    const int h  = blockIdx.y;
    const int b  = blockIdx.z;
    const int t = threadIdx.x, w = t >> 5, lane = t & 31;
    const int g = lane >> 2, c = lane & 3;
    const int pg = (g >> 1) + (g & 1) * 4;     // key-group permutation p(g)
    const int row0 = q0 + w * 16 + g, row1 = row0 + 8;
    const bool v0 = row0 < S_, v1 = row1 < S_;

    const float* qb = g_q + (size_t)b * S_ * C_ + h * HD_;
    const float* kb = g_k + (size_t)b * S_ * C_ + h * HD_;
    const float* mb = maskp + (size_t)b * S_ * S_;

    // Q fragments (persist)
    uint32_t qa[4][4];
    #pragma unroll
    for (int ks = 0; ks < 4; ks++) {
        int d0 = ks * 8 + c;
        qa[ks][0] = v0 ? tf32r(qb[(size_t)row0 * C_ + d0    ]) : 0u;
        qa[ks][1] = v1 ? tf32r(qb[(size_t)row1 * C_ + d0    ]) : 0u;
        qa[ks][2] = v0 ? tf32r(qb[(size_t)row0 * C_ + d0 + 4]) : 0u;
        qa[ks][3] = v1 ? tf32r(qb[(size_t)row1 * C_ + d0 + 4]) : 0u;
    }

    // K prefetch indices: thread covers elems t and t+256 of 512 (64 rows x 8 seg)
    const int kr0 = t >> 3, ksg = t & 7;
    const int kr1 = kr0 + 32;

    // mask cp.async destinations (R4 layout: per-warp 16-row blocks)
    uint32_t msmem[8];
    {
        uint32_t base = smem_u32(ds + MSK_F);
        #pragma unroll
        for (int jj = 0; jj < 8; jj++) {
            int j = jj * 32 + lane;
            int row = j >> 4, col4 = j & 15;
            msmem[jj] = base + (uint32_t)(((w * 16 + row) * 68 + col4 * 4) * 4);
        }
    }
    const uint32_t msbuf_bytes = MSK_BUF * 4u;

    // issue mask(0) prefetch
    #pragma unroll
    for (int jj = 0; jj < 8; jj++) {
        int j = jj * 32 + lane;
        int row = j >> 4, col4 = j & 15;
        int grow = q0 + w * 16 + row;
        uint32_t sz = (grow < S_) ? 16u : 0u;
        const float* src = mb + (size_t)(sz ? grow : 0) * S_ + col4 * 4;
        CP_ASYNC16(msmem[jj], src, sz);
    }
    CP_COMMIT();

    // ---- load K tile 0 into Ks + KsT (keys 0..63 all valid) ----
    {
        float4 a0 = *(const float4*)(kb + (size_t)kr0 * C_ + ksg * 4);
        float4 a1 = *(const float4*)(kb + (size_t)kr1 * C_ + ksg * 4);
        uint4 u;
        u.x = tf32r(a0.x); u.y = tf32r(a0.y); u.z = tf32r(a0.z); u.w = tf32r(a0.w);
        *(uint4*)&ds[kr0 * 36 + ksg * 4] = u;
        ds[KST_F + (ksg*4 + 0) * 68 + kr0] = __uint_as_float(u.x);
        ds[KST_F + (ksg*4 + 1) * 68 + kr0] = __uint_as_float(u.y);
        ds[KST_F + (ksg*4 + 2) * 68 + kr0] = __uint_as_float(u.z);
        ds[KST_F + (ksg*4 + 3) * 68 + kr0] = __uint_as_float(u.w);
        u.x = tf32r(a1.x); u.y = tf32r(a1.y); u.z = tf32r(a1.z); u.w = tf32r(a1.w);
        *(uint4*)&ds[kr1 * 36 + ksg * 4] = u;
        ds[KST_F + (ksg*4 + 0) * 68 + kr1] = __uint_as_float(u.x);
        ds[KST_F + (ksg*4 + 1) * 68 + kr1] = __uint_as_float(u.y);
        ds[KST_F + (ksg*4 + 2) * 68 + kr1] = __uint_as_float(u.z);
        ds[KST_F + (ksg*4 + 3) * 68 + kr1] = __uint_as_float(u.w);
    }

    float o[4][4] = {};
    float den0 = 0.f, den1 = 0.f;

    for (int kt = 0; kt < NT_TILES; kt++) {
        const int k0 = kt * 64;
        const int cur = kt & 1;
        CP_WAIT0();
        __syncthreads();   // Ks/KsT[cur] + mask[cur] ready

        // ---- prefetch next tile (mask via cp.async, K into regs) ----
        float4 nk0v, nk1v;
        if (kt < NT_TILES - 1) {
            const int nk0 = k0 + 64;
            uint32_t boff = (uint32_t)(cur ^ 1) * msbuf_bytes;
            #pragma unroll
            for (int jj = 0; jj < 8; jj++) {
                int j = jj * 32 + lane;
                int row = j >> 4, col4 = j & 15;
                int grow = q0 + w * 16 + row;
                int gcol = nk0 + col4 * 4;
                uint32_t sz = (grow < S_ && gcol < S_) ? 16u : 0u;
                const float* src = mb + (size_t)(sz ? grow : 0) * S_ + (sz ? gcol : 0);
                CP_ASYNC16(msmem[jj] + boff, src, sz);
            }
            CP_COMMIT();
            int gk0 = nk0 + kr0, gk1 = nk0 + kr1;
            nk0v = make_float4(0.f, 0.f, 0.f, 0.f);
            nk1v = nk0v;
            if (gk0 < S_) nk0v = *(const float4*)(kb + (size_t)gk0 * C_ + ksg * 4);
            if (gk1 < S_) nk1v = *(const float4*)(kb + (size_t)gk1 * C_ + ksg * 4);
        }

        const float* Ksc  = ds + cur * 2304;
        const float* KsTc = ds + KST_F + cur * 2176;
        const float* Msc  = ds + MSK_F + (size_t)cur * MSK_BUF + (size_t)w * 16 * 68;

        #pragma unroll
        for (int nt = 0; nt < 8; nt++) {
            // MMA1 with permuted B rows: S column j holds key p(j)
            float s[4] = {0.f, 0.f, 0.f, 0.f};
            #pragma unroll
            for (int ks = 0; ks < 4; ks++) {
                uint32_t b0 = __float_as_uint(Ksc[(nt*8 + pg) * 36 + ks*8 + c    ]);
                uint32_t b1 = __float_as_uint(Ksc[(nt*8 + pg) * 36 + ks*8 + c + 4]);
                mma_tf32(s, qa[ks], b0, b1);
            }
            // s[0]=row0/key c, s[1]=row0/key c+4, s[2]=row1/key c, s[3]=row1/key c+4
            const bool kv = (k0 + nt * 8) < S_;
            float w00 = 0.f, w01 = 0.f, w02 = 0.f, w03 = 0.f;
            if (kv) {
                if (v0) {
                    float ma = Msc[g * 68 + nt*8 + c    ];
                    float mbv = Msc[g * 68 + nt*8 + c + 4];
                    w00 = (ma  + 1e-6f) * pexp(s[0]);
                    w01 = (mbv + 1e-6f) * pexp(s[1]);
                }
                if (v1) {
                    float ma = Msc[(g + 8) * 68 + nt*8 + c    ];
                    float mbv = Msc[(g + 8) * 68 + nt*8 + c + 4];
                    w02 = (ma  + 1e-6f) * pexp(s[2]);
                    w03 = (mbv + 1e-6f) * pexp(s[3]);
                }
            }
            den0 += w00 + w01;
            den1 += w02 + w03;

            // C-frag IS the A-frag (register renaming only):
            // a0 = P[row0][key c], a1 = P[row1][key c], a2 = P[row0][key c+4],
            // a3 = P[row1][key c+4]
            uint32_t a[4];
            a[0] = tf32r(w00);
            a[1] = tf32r(w02);
            a[2] = tf32r(w01);
            a[3] = tf32r(w03);

            // MMA2: O += P(group nt) * K rows nt*8..+7 (conflict-free KsT)
            #pragma unroll
            for (int nt2 = 0; nt2 < 4; nt2++) {
                uint32_t b0 = __float_as_uint(KsTc[(nt2*8 + g) * 68 + nt*8 + c    ]);
                uint32_t b1 = __float_as_uint(KsTc[(nt2*8 + g) * 68 + nt*8 + c + 4]);
                mma_tf32(o[nt2], a, b0, b1);
            }
        }

        // ---- store prefetched K(kt+1) into the other buffers ----
        if (kt < NT_TILES - 1) {
            float* Ksn  = ds + (cur ^ 1) * 2304;
            float* KsTn = ds + KST_F + (cur ^ 1) * 2176;
            uint4 u;
            u.x = tf32r(nk0v.x); u.y = tf32r(nk0v.y); u.z = tf32r(nk0v.z); u.w = tf32r(nk0v.w);
            *(uint4*)&Ksn[kr0 * 36 + ksg * 4] = u;
            KsTn[(ksg*4 + 0) * 68 + kr0] = __uint_as_float(u.x);
            KsTn[(ksg*4 + 1) * 68 + kr0] = __uint_as_float(u.y);
            KsTn[(ksg*4 + 2) * 68 + kr0] = __uint_as_float(u.z);
            KsTn[(ksg*4 + 3) * 68 + kr0] = __uint_as_float(u.w);
            u.x = tf32r(nk1v.x); u.y = tf32r(nk1v.y); u.z = tf32r(nk1v.z); u.w = tf32r(nk1v.w);
            *(uint4*)&Ksn[kr1 * 36 + ksg * 4] = u;
            KsTn[(ksg*4 + 0) * 68 + kr1] = __uint_as_float(u.x);
            KsTn[(ksg*4 + 1) * 68 + kr1] = __uint_as_float(u.y);
            KsTn[(ksg*4 + 2) * 68 + kr1] = __uint_as_float(u.z);
            KsTn[(ksg*4 + 3) * 68 + kr1] = __uint_as_float(u.w);
        }
    }

    // denominator: reduce across the 4 lanes of each row-group
    den0 += __shfl_xor_sync(0xffffffffu, den0, 1);
    den0 += __shfl_xor_sync(0xffffffffu, den0, 2);
    den1 += __shfl_xor_sync(0xffffffffu, den1, 1);
    den1 += __shfl_xor_sync(0xffffffffu, den1, 2);
    const float inv0 = v0 ? 1.f / den0 : 0.f;
    const float inv1 = v1 ? 1.f / den1 : 0.f;

    float* ob0 = g_att + ((size_t)b * S_ + row0) * C_ + h * HD_;
    float* ob1 = g_att + ((size_t)b * S_ + row1) * C_ + h * HD_;
    #pragma unroll
    for (int nt2 = 0; nt2 < 4; nt2++) {
        if (v0) {
            float2 r;
            r.x = o[nt2][0] * inv0;
            r.y = o[nt2][1] * inv0;
            *(float2*)(ob0 + nt2 * 8 + 2 * c) = r;
        }
        if (v1) {
            float2 r;
            r.x = o[nt2][2] * inv1;
            r.y = o[nt2][3] * inv1;
            *(float2*)(ob1 + nt2 * 8 + 2 * c) = r;
        }
    }
}

// ---------------------------------------------------------------------------
// LEPE: depthwise 5x5 conv on v[:, QN:, :], pad 2, added into g_att[:, QN:, :]
// ---------------------------------------------------------------------------
__global__ __launch_bounds__(256) void lepe_kernel(
    const float* __restrict__ lw, const float* __restrict__ lb)
{
    int p = blockIdx.x;
    int b = blockIdx.y;
    int c = threadIdx.x;
    int i = p / IMW_, j = p % IMW_;

    float acc = lb[c];
    #pragma unroll
    for (int u = 0; u < 5; u++) {
        int ii = i + u - 2;
        if (ii < 0 || ii >= IMH_) continue;
        #pragma unroll
        for (int v = 0; v < 5; v++) {
            int jj = j + v - 2;
            if (jj < 0 || jj >= IMW_) continue;
            int src = QN_ + ii * IMW_ + jj;
            acc += g_v[((size_t)b * S_ + src) * C_ + c] * lw[(u * 5 + v) * C_ + c];
        }
    }
    g_att[((size_t)b * S_ + QN_ + p) * C_ + c] += acc;
}

// ---------------------------------------------------------------------------
extern "C" void kernel_launch(void* const* d_in, const int* in_sizes, int n_in,
                              void* d_out, int out_size)
{
    const float* x    = (const float*)d_in[0];
    const float* mask = (const float*)d_in[1];
    const float* wq   = (const float*)d_in[2];
    const float* bq   = (const float*)d_in[3];
    const float* wk   = (const float*)d_in[4];
    const float* bk   = (const float*)d_in[5];
    const float* wv   = (const float*)d_in[6];
    const float* bv   = (const float*)d_in[7];
    const float* lw   = (const float*)d_in[8];
    const float* lb   = (const float*)d_in[9];
    const float* wo   = (const float*)d_in[10];
    const float* bo   = (const float*)d_in[11];
    float* out = (float*)d_out;

    const int M = B_ * S_;                       // 6288
    dim3 gg((M + 127) / 128, C_ / 64);           // 50 x 4

    static int smem_set = 0;
    if (!smem_set) {
        cudaFuncSetAttribute(attn_mma_kernel,
                             cudaFuncAttributeMaxDynamicSharedMemorySize, SMEM_ATTN);
        smem_set = 1;
    }

    gemm_mma_kernel<<<gg, 256>>>(x, wq, bq, nullptr, 0, 0, M, 1.f);
    gemm_mma_kernel<<<gg, 256>>>(x, wk, bk, nullptr, 0, 1, M, SCALE_);
    gemm_mma_kernel<<<gg, 256>>>(x, wv, bv, nullptr, 0, 2, M, 1.f);

    attn_mma_kernel<<<dim3((S_ + 127) / 128, H_, B_), 256, SMEM_ATTN>>>(mask);

    lepe_kernel<<<dim3(IMH_ * IMW_, B_), 256>>>(lw, lb);

    gemm_mma_kernel<<<gg, 256>>>(nullptr, wo, bo, out, 1, 3, M, 1.f);
}

// round 9
// speedup vs baseline: 1.9884x; 1.0785x over previous
#include <cuda_runtime.h>
#include <cstdint>

// ---------------------------------------------------------------------------
// MaskAttention: B=2, S=3144, C=256, H=8, HD=32, QN=8, image 56x56, lepe 5x5 dw
// R9: R8 inner loop + split-K attention (2 key-splits, additive partials,
//     finalize kernel) to fix wave quantization (400 CTAs @2/SM = 1.35 waves
//     -> 800 half-CTAs = 2.7 waves, efficiency 0.68 -> 0.90).
//     QKV projections fused into one launch.
// softmax(qk + log(m+eps)) == (m+eps)*exp(qk) / sum_k (m+eps)*exp(qk)
// ---------------------------------------------------------------------------

#define B_   2
#define S_   3144
#define C_   256
#define H_   8
#define HD_  32
#define QN_  8
#define IMH_ 56
#define IMW_ 56
#define SCALE_ 0.17677669529663687f   // 32^-0.5

__device__ __align__(16) float g_q[B_*S_*C_];
__device__ __align__(16) float g_k[B_*S_*C_];
__device__ __align__(16) float g_v[B_*S_*C_];
__device__ __align__(16) float g_att[B_*S_*C_];
__device__ __align__(16) float g_on[2*B_*S_*C_];   // split partial numerators
__device__ __align__(16) float g_dn[2*B_*H_*S_];   // split partial denominators

// ----------------------------- helpers -------------------------------------
__device__ __forceinline__ uint32_t tf32r(float x) {
    uint32_t r;
    asm("cvt.rna.tf32.f32 %0, %1;" : "=r"(r) : "f"(x));
    return r;
}
__device__ __forceinline__ void mma_tf32(float* d, const uint32_t* a,
                                         uint32_t b0, uint32_t b1) {
    asm volatile(
        "mma.sync.aligned.m16n8k8.row.col.f32.tf32.tf32.f32 "
        "{%0,%1,%2,%3}, {%4,%5,%6,%7}, {%8,%9}, {%0,%1,%2,%3};"
        : "+f"(d[0]), "+f"(d[1]), "+f"(d[2]), "+f"(d[3])
        : "r"(a[0]), "r"(a[1]), "r"(a[2]), "r"(a[3]), "r"(b0), "r"(b1));
}
__device__ __forceinline__ float pexp(float s) {
    float p = fmaf(s, 1.f/24.f, 1.f/6.f);
    p = fmaf(p, s, 0.5f);
    p = fmaf(p, s, 1.f);
    return fmaf(p, s, 1.f);
}
__device__ __forceinline__ uint32_t smem_u32(const void* p) {
    uint32_t a;
    asm("{ .reg .u64 t; cvta.to.shared.u64 t, %1; cvt.u32.u64 %0, t; }"
        : "=r"(a) : "l"(p));
    return a;
}
#define CP_ASYNC16(dst, src, sz) \
    asm volatile("cp.async.ca.shared.global [%0], [%1], 16, %2;" \
                 :: "r"(dst), "l"(src), "r"(sz) : "memory")
#define CP_COMMIT() asm volatile("cp.async.commit_group;" ::: "memory")
#define CP_WAIT0()  asm volatile("cp.async.wait_group 0;" ::: "memory")

// ---------------------------------------------------------------------------
// Fused QKV projection: z selects (wq,bq)->g_q, (wk,bk)*SCALE->g_k, (wv,bv)->g_v
// ---------------------------------------------------------------------------
__global__ __launch_bounds__(256, 2) void qkv_gemm_kernel(
    const float* __restrict__ x,
    const float* __restrict__ wq, const float* __restrict__ bq,
    const float* __restrict__ wk, const float* __restrict__ bk,
    const float* __restrict__ wv, const float* __restrict__ bv)
{
    __shared__ float As[128][36];
    __shared__ float Ws[64][36];
    const int sel = blockIdx.z;
    const float* W    = (sel == 0) ? wq : (sel == 1) ? wk : wv;
    const float* bias = (sel == 0) ? bq : (sel == 1) ? bk : bv;
    float* Cm         = (sel == 0) ? g_q : (sel == 1) ? g_k : g_v;
    const float scale = (sel == 1) ? SCALE_ : 1.f;
    const int M = B_ * S_;

    const int m0 = blockIdx.x * 128, n0 = blockIdx.y * 64;
    const int t = threadIdx.x, w = t >> 5, lane = t & 31;
    const int g = lane >> 2, c = lane & 3;
    const int row0 = m0 + w * 16 + g, row1 = row0 + 8;

    float acc[8][4] = {};

    for (int k0 = 0; k0 < 256; k0 += 32) {
        __syncthreads();
        #pragma unroll
        for (int i = t; i < 1024; i += 256) {
            int r = i >> 3, sg = i & 7;
            int gm = m0 + r;
            float4 vv = make_float4(0.f, 0.f, 0.f, 0.f);
            if (gm < M) vv = *(const float4*)(x + (size_t)gm * 256 + k0 + sg * 4);
            uint4 u;
            u.x = tf32r(vv.x); u.y = tf32r(vv.y); u.z = tf32r(vv.z); u.w = tf32r(vv.w);
            *(uint4*)&As[r][sg * 4] = u;
        }
        #pragma unroll
        for (int i = t; i < 512; i += 256) {
            int r = i >> 3, sg = i & 7;
            float4 vv = *(const float4*)(W + (size_t)(n0 + r) * 256 + k0 + sg * 4);
            uint4 u;
            u.x = tf32r(vv.x); u.y = tf32r(vv.y); u.z = tf32r(vv.z); u.w = tf32r(vv.w);
            *(uint4*)&Ws[r][sg * 4] = u;
        }
        __syncthreads();

        #pragma unroll
        for (int ks = 0; ks < 4; ks++) {
            uint32_t a[4];
            a[0] = __float_as_uint(As[w*16 + g    ][ks*8 + c    ]);
            a[1] = __float_as_uint(As[w*16 + g + 8][ks*8 + c    ]);
            a[2] = __float_as_uint(As[w*16 + g    ][ks*8 + c + 4]);
            a[3] = __float_as_uint(As[w*16 + g + 8][ks*8 + c + 4]);
            #pragma unroll
            for (int nt = 0; nt < 8; nt++) {
                uint32_t b0 = __float_as_uint(Ws[nt*8 + g][ks*8 + c    ]);
                uint32_t b1 = __float_as_uint(Ws[nt*8 + g][ks*8 + c + 4]);
                mma_tf32(acc[nt], a, b0, b1);
            }
        }
    }

    #pragma unroll
    for (int nt = 0; nt < 8; nt++) {
        int n = n0 + nt * 8 + 2 * c;
        float2 bb = *(const float2*)(bias + n);
        if (row0 < M) {
            float2 r;
            r.x = (acc[nt][0] + bb.x) * scale;
            r.y = (acc[nt][1] + bb.y) * scale;
            *(float2*)(Cm + (size_t)row0 * 256 + n) = r;
        }
        if (row1 < M) {
            float2 r;
            r.x = (acc[nt][2] + bb.x) * scale;
            r.y = (acc[nt][3] + bb.y) * scale;
            *(float2*)(Cm + (size_t)row1 * 256 + n) = r;
        }
    }
}

// ---------------------------------------------------------------------------
// Output projection GEMM: out[M,256] = g_att @ wo^T + bo
// ---------------------------------------------------------------------------
__global__ __launch_bounds__(256, 2) void out_gemm_kernel(
    const float* __restrict__ W, const float* __restrict__ bias,
    float* __restrict__ Cext)
{
    __shared__ float As[128][36];
    __shared__ float Ws[64][36];
    const int M = B_ * S_;
    const int m0 = blockIdx.x * 128, n0 = blockIdx.y * 64;
    const int t = threadIdx.x, w = t >> 5, lane = t & 31;
    const int g = lane >> 2, c = lane & 3;
    const int row0 = m0 + w * 16 + g, row1 = row0 + 8;

    float acc[8][4] = {};

    for (int k0 = 0; k0 < 256; k0 += 32) {
        __syncthreads();
        #pragma unroll
        for (int i = t; i < 1024; i += 256) {
            int r = i >> 3, sg = i & 7;
            int gm = m0 + r;
            float4 vv = make_float4(0.f, 0.f, 0.f, 0.f);
            if (gm < M) vv = *(const float4*)(g_att + (size_t)gm * 256 + k0 + sg * 4);
            uint4 u;
            u.x = tf32r(vv.x); u.y = tf32r(vv.y); u.z = tf32r(vv.z); u.w = tf32r(vv.w);
            *(uint4*)&As[r][sg * 4] = u;
        }
        #pragma unroll
        for (int i = t; i < 512; i += 256) {
            int r = i >> 3, sg = i & 7;
            float4 vv = *(const float4*)(W + (size_t)(n0 + r) * 256 + k0 + sg * 4);
            uint4 u;
            u.x = tf32r(vv.x); u.y = tf32r(vv.y); u.z = tf32r(vv.z); u.w = tf32r(vv.w);
            *(uint4*)&Ws[r][sg * 4] = u;
        }
        __syncthreads();

        #pragma unroll
        for (int ks = 0; ks < 4; ks++) {
            uint32_t a[4];
            a[0] = __float_as_uint(As[w*16 + g    ][ks*8 + c    ]);
            a[1] = __float_as_uint(As[w*16 + g + 8][ks*8 + c    ]);
            a[2] = __float_as_uint(As[w*16 + g    ][ks*8 + c + 4]);
            a[3] = __float_as_uint(As[w*16 + g + 8][ks*8 + c + 4]);
            #pragma unroll
            for (int nt = 0; nt < 8; nt++) {
                uint32_t b0 = __float_as_uint(Ws[nt*8 + g][ks*8 + c    ]);
                uint32_t b1 = __float_as_uint(Ws[nt*8 + g][ks*8 + c + 4]);
                mma_tf32(acc[nt], a, b0, b1);
            }
        }
    }

    #pragma unroll
    for (int nt = 0; nt < 8; nt++) {
        int n = n0 + nt * 8 + 2 * c;
        float2 bb = *(const float2*)(bias + n);
        if (row0 < M) {
            float2 r;
            r.x = acc[nt][0] + bb.x;
            r.y = acc[nt][1] + bb.y;
            *(float2*)(Cext + (size_t)row0 * 256 + n) = r;
        }
        if (row1 < M) {
            float2 r;
            r.x = acc[nt][2] + bb.x;
            r.y = acc[nt][3] + bb.y;
            *(float2*)(Cext + (size_t)row1 * 256 + n) = r;
        }
    }
}

// ---------------------------------------------------------------------------
// Attention (split-K). CTA = 128 queries x 1 head x 25 key tiles (one split).
// grid (25, 8, B*2): z = b*2 + split. Writes unnormalized partials.
// Smem layout identical to R8.
// ---------------------------------------------------------------------------
#define KST_F   4608
#define MSK_F   8960
#define MSK_BUF 8704
#define SMEM_ATTN 105472
#define NT_TILES 50
#define SPLIT_T  25

__global__ __launch_bounds__(256, 2) void attn_mma_kernel(const float* __restrict__ maskp)
{
    extern __shared__ __align__(16) float ds[];

    const int q0 = blockIdx.x * 128;
    const int h  = blockIdx.y;
    const int b  = blockIdx.z >> 1;
    const int split = blockIdx.z & 1;
    const int kt0 = split * SPLIT_T, kt1 = kt0 + SPLIT_T;
    const int t = threadIdx.x, w = t >> 5, lane = t & 31;
    const int g = lane >> 2, c = lane & 3;
    const int pg = (g >> 1) + (g & 1) * 4;     // key-group permutation p(g)
    const int row0 = q0 + w * 16 + g, row1 = row0 + 8;
    const bool v0 = row0 < S_, v1 = row1 < S_;

    const float* qb = g_q + (size_t)b * S_ * C_ + h * HD_;
    const float* kb = g_k + (size_t)b * S_ * C_ + h * HD_;
    const float* mb = maskp + (size_t)b * S_ * S_;

    // Q fragments (persist)
    uint32_t qa[4][4];
    #pragma unroll
    for (int ks = 0; ks < 4; ks++) {
        int d0 = ks * 8 + c;
        qa[ks][0] = v0 ? tf32r(qb[(size_t)row0 * C_ + d0    ]) : 0u;
        qa[ks][1] = v1 ? tf32r(qb[(size_t)row1 * C_ + d0    ]) : 0u;
        qa[ks][2] = v0 ? tf32r(qb[(size_t)row0 * C_ + d0 + 4]) : 0u;
        qa[ks][3] = v1 ? tf32r(qb[(size_t)row1 * C_ + d0 + 4]) : 0u;
    }

    const int kr0 = t >> 3, ksg = t & 7;
    const int kr1 = kr0 + 32;

    uint32_t msmem[8];
    {
        uint32_t base = smem_u32(ds + MSK_F);
        #pragma unroll
        for (int jj = 0; jj < 8; jj++) {
            int j = jj * 32 + lane;
            int row = j >> 4, col4 = j & 15;
            msmem[jj] = base + (uint32_t)(((w * 16 + row) * 68 + col4 * 4) * 4);
        }
    }
    const uint32_t msbuf_bytes = MSK_BUF * 4u;

    // issue mask(kt0) prefetch into buffer (kt0 & 1)
    {
        uint32_t boff = (uint32_t)(kt0 & 1) * msbuf_bytes;
        #pragma unroll
        for (int jj = 0; jj < 8; jj++) {
            int j = jj * 32 + lane;
            int row = j >> 4, col4 = j & 15;
            int grow = q0 + w * 16 + row;
            int gcol = kt0 * 64 + col4 * 4;
            uint32_t sz = (grow < S_) ? 16u : 0u;
            const float* src = mb + (size_t)(sz ? grow : 0) * S_ + gcol;
            CP_ASYNC16(msmem[jj] + boff, src, sz);
        }
        CP_COMMIT();
    }

    // ---- load K tile kt0 into Ks/KsT buffer (kt0 & 1); rows all < S_ ----
    {
        const int base = kt0 * 64;
        float* Ks0  = ds + (kt0 & 1) * 2304;
        float* KsT0 = ds + KST_F + (kt0 & 1) * 2176;
        float4 a0 = *(const float4*)(kb + (size_t)(base + kr0) * C_ + ksg * 4);
        float4 a1 = *(const float4*)(kb + (size_t)(base + kr1) * C_ + ksg * 4);
        uint4 u;
        u.x = tf32r(a0.x); u.y = tf32r(a0.y); u.z = tf32r(a0.z); u.w = tf32r(a0.w);
        *(uint4*)&Ks0[kr0 * 36 + ksg * 4] = u;
        KsT0[(ksg*4 + 0) * 68 + kr0] = __uint_as_float(u.x);
        KsT0[(ksg*4 + 1) * 68 + kr0] = __uint_as_float(u.y);
        KsT0[(ksg*4 + 2) * 68 + kr0] = __uint_as_float(u.z);
        KsT0[(ksg*4 + 3) * 68 + kr0] = __uint_as_float(u.w);
        u.x = tf32r(a1.x); u.y = tf32r(a1.y); u.z = tf32r(a1.z); u.w = tf32r(a1.w);
        *(uint4*)&Ks0[kr1 * 36 + ksg * 4] = u;
        KsT0[(ksg*4 + 0) * 68 + kr1] = __uint_as_float(u.x);
        KsT0[(ksg*4 + 1) * 68 + kr1] = __uint_as_float(u.y);
        KsT0[(ksg*4 + 2) * 68 + kr1] = __uint_as_float(u.z);
        KsT0[(ksg*4 + 3) * 68 + kr1] = __uint_as_float(u.w);
    }

    float o[4][4] = {};
    float den0 = 0.f, den1 = 0.f;

    for (int kt = kt0; kt < kt1; kt++) {
        const int k0 = kt * 64;
        const int cur = kt & 1;
        CP_WAIT0();
        __syncthreads();

        // ---- prefetch next tile ----
        float4 nk0v, nk1v;
        if (kt < kt1 - 1) {
            const int nk0 = k0 + 64;
            uint32_t boff = (uint32_t)(cur ^ 1) * msbuf_bytes;
            #pragma unroll
            for (int jj = 0; jj < 8; jj++) {
                int j = jj * 32 + lane;
                int row = j >> 4, col4 = j & 15;
                int grow = q0 + w * 16 + row;
                int gcol = nk0 + col4 * 4;
                uint32_t sz = (grow < S_ && gcol < S_) ? 16u : 0u;
                const float* src = mb + (size_t)(sz ? grow : 0) * S_ + (sz ? gcol : 0);
                CP_ASYNC16(msmem[jj] + boff, src, sz);
            }
            CP_COMMIT();
            int gk0 = nk0 + kr0, gk1 = nk0 + kr1;
            nk0v = make_float4(0.f, 0.f, 0.f, 0.f);
            nk1v = nk0v;
            if (gk0 < S_) nk0v = *(const float4*)(kb + (size_t)gk0 * C_ + ksg * 4);
            if (gk1 < S_) nk1v = *(const float4*)(kb + (size_t)gk1 * C_ + ksg * 4);
        }

        const float* Ksc  = ds + cur * 2304;
        const float* KsTc = ds + KST_F + cur * 2176;
        const float* Msc  = ds + MSK_F + (size_t)cur * MSK_BUF + (size_t)w * 16 * 68;

        #pragma unroll
        for (int nt = 0; nt < 8; nt++) {
            float s[4] = {0.f, 0.f, 0.f, 0.f};
            #pragma unroll
            for (int ks = 0; ks < 4; ks++) {
                uint32_t b0 = __float_as_uint(Ksc[(nt*8 + pg) * 36 + ks*8 + c    ]);
                uint32_t b1 = __float_as_uint(Ksc[(nt*8 + pg) * 36 + ks*8 + c + 4]);
                mma_tf32(s, qa[ks], b0, b1);
            }
            const bool kv = (k0 + nt * 8) < S_;
            float w00 = 0.f, w01 = 0.f, w02 = 0.f, w03 = 0.f;
            if (kv) {
                if (v0) {
                    float ma  = Msc[g * 68 + nt*8 + c    ];
                    float mbv = Msc[g * 68 + nt*8 + c + 4];
                    w00 = (ma  + 1e-6f) * pexp(s[0]);
                    w01 = (mbv + 1e-6f) * pexp(s[1]);
                }
                if (v1) {
                    float ma  = Msc[(g + 8) * 68 + nt*8 + c    ];
                    float mbv = Msc[(g + 8) * 68 + nt*8 + c + 4];
                    w02 = (ma  + 1e-6f) * pexp(s[2]);
                    w03 = (mbv + 1e-6f) * pexp(s[3]);
                }
            }
            den0 += w00 + w01;
            den1 += w02 + w03;

            uint32_t a[4];
            a[0] = tf32r(w00);
            a[1] = tf32r(w02);
            a[2] = tf32r(w01);
            a[3] = tf32r(w03);

            #pragma unroll
            for (int nt2 = 0; nt2 < 4; nt2++) {
                uint32_t b0 = __float_as_uint(KsTc[(nt2*8 + g) * 68 + nt*8 + c    ]);
                uint32_t b1 = __float_as_uint(KsTc[(nt2*8 + g) * 68 + nt*8 + c + 4]);
                mma_tf32(o[nt2], a, b0, b1);
            }
        }

        if (kt < kt1 - 1) {
            float* Ksn  = ds + (cur ^ 1) * 2304;
            float* KsTn = ds + KST_F + (cur ^ 1) * 2176;
            uint4 u;
            u.x = tf32r(nk0v.x); u.y = tf32r(nk0v.y); u.z = tf32r(nk0v.z); u.w = tf32r(nk0v.w);
            *(uint4*)&Ksn[kr0 * 36 + ksg * 4] = u;
            KsTn[(ksg*4 + 0) * 68 + kr0] = __uint_as_float(u.x);
            KsTn[(ksg*4 + 1) * 68 + kr0] = __uint_as_float(u.y);
            KsTn[(ksg*4 + 2) * 68 + kr0] = __uint_as_float(u.z);
            KsTn[(ksg*4 + 3) * 68 + kr0] = __uint_as_float(u.w);
            u.x = tf32r(nk1v.x); u.y = tf32r(nk1v.y); u.z = tf32r(nk1v.z); u.w = tf32r(nk1v.w);
            *(uint4*)&Ksn[kr1 * 36 + ksg * 4] = u;
            KsTn[(ksg*4 + 0) * 68 + kr1] = __uint_as_float(u.x);
            KsTn[(ksg*4 + 1) * 68 + kr1] = __uint_as_float(u.y);
            KsTn[(ksg*4 + 2) * 68 + kr1] = __uint_as_float(u.z);
            KsTn[(ksg*4 + 3) * 68 + kr1] = __uint_as_float(u.w);
        }
    }

    // quad-reduce denominators (all 4 lanes end with the sum)
    den0 += __shfl_xor_sync(0xffffffffu, den0, 1);
    den0 += __shfl_xor_sync(0xffffffffu, den0, 2);
    den1 += __shfl_xor_sync(0xffffffffu, den1, 1);
    den1 += __shfl_xor_sync(0xffffffffu, den1, 2);

    // ---- write unnormalized partials ----
    float* on = g_on + (size_t)split * B_ * S_ * C_;
    float* ob0 = on + ((size_t)b * S_ + row0) * C_ + h * HD_;
    float* ob1 = on + ((size_t)b * S_ + row1) * C_ + h * HD_;
    #pragma unroll
    for (int nt2 = 0; nt2 < 4; nt2++) {
        if (v0) {
            float2 r; r.x = o[nt2][0]; r.y = o[nt2][1];
            *(float2*)(ob0 + nt2 * 8 + 2 * c) = r;
        }
        if (v1) {
            float2 r; r.x = o[nt2][2]; r.y = o[nt2][3];
            *(float2*)(ob1 + nt2 * 8 + 2 * c) = r;
        }
    }
    if (c == 0) {
        float* dn = g_dn + (size_t)split * B_ * H_ * S_ + ((size_t)b * H_ + h) * S_;
        if (v0) dn[row0] = den0;
        if (v1) dn[row1] = den1;
    }
}

// ---------------------------------------------------------------------------
// Finalize: g_att = (O0 + O1) / (d0 + d1)
// ---------------------------------------------------------------------------
__global__ __launch_bounds__(256) void finalize_kernel()
{
    const int s = blockIdx.x, b = blockIdx.y, c = threadIdx.x;
    const int h = c >> 5;
    const size_t di = ((size_t)b * H_ + h) * S_ + s;
    const float den = g_dn[di] + g_dn[(size_t)B_ * H_ * S_ + di];
    const size_t oi = ((size_t)b * S_ + s) * C_ + c;
    g_att[oi] = (g_on[oi] + g_on[(size_t)B_ * S_ * C_ + oi]) / den;
}

// ---------------------------------------------------------------------------
// LEPE: depthwise 5x5 conv on v[:, QN:, :], pad 2, added into g_att[:, QN:, :]
// ---------------------------------------------------------------------------
__global__ __launch_bounds__(256) void lepe_kernel(
    const float* __restrict__ lw, const float* __restrict__ lb)
{
    int p = blockIdx.x;
    int b = blockIdx.y;
    int c = threadIdx.x;
    int i = p / IMW_, j = p % IMW_;

    float acc = lb[c];
    #pragma unroll
    for (int u = 0; u < 5; u++) {
        int ii = i + u - 2;
        if (ii < 0 || ii >= IMH_) continue;
        #pragma unroll
        for (int v = 0; v < 5; v++) {
            int jj = j + v - 2;
            if (jj < 0 || jj >= IMW_) continue;
            int src = QN_ + ii * IMW_ + jj;
            acc += g_v[((size_t)b * S_ + src) * C_ + c] * lw[(u * 5 + v) * C_ + c];
        }
    }
    g_att[((size_t)b * S_ + QN_ + p) * C_ + c] += acc;
}

// ---------------------------------------------------------------------------
extern "C" void kernel_launch(void* const* d_in, const int* in_sizes, int n_in,
                              void* d_out, int out_size)
{
    const float* x    = (const float*)d_in[0];
    const float* mask = (const float*)d_in[1];
    const float* wq   = (const float*)d_in[2];
    const float* bq   = (const float*)d_in[3];
    const float* wk   = (const float*)d_in[4];
    const float* bk   = (const float*)d_in[5];
    const float* wv   = (const float*)d_in[6];
    const float* bv   = (const float*)d_in[7];
    const float* lw   = (const float*)d_in[8];
    const float* lb   = (const float*)d_in[9];
    const float* wo   = (const float*)d_in[10];
    const float* bo   = (const float*)d_in[11];
    float* out = (float*)d_out;

    const int M = B_ * S_;                       // 6288
    dim3 gqkv((M + 127) / 128, C_ / 64, 3);      // 50 x 4 x 3
    dim3 go((M + 127) / 128, C_ / 64);           // 50 x 4

    static int smem_set = 0;
    if (!smem_set) {
        cudaFuncSetAttribute(attn_mma_kernel,
                             cudaFuncAttributeMaxDynamicSharedMemorySize, SMEM_ATTN);
        smem_set = 1;
    }

    qkv_gemm_kernel<<<gqkv, 256>>>(x, wq, bq, wk, bk, wv, bv);

    attn_mma_kernel<<<dim3((S_ + 127) / 128, H_, B_ * 2), 256, SMEM_ATTN>>>(mask);

    finalize_kernel<<<dim3(S_, B_), 256>>>();

    lepe_kernel<<<dim3(IMH_ * IMW_, B_), 256>>>(lw, lb);

    out_gemm_kernel<<<go, 256>>>(wo, bo, out);
}